// round 3
// baseline (speedup 1.0000x reference)
#include <cuda_runtime.h>
#include <cuda_bf16.h>
#include <cstdint>

// ============================================================================
// out = LayerNorm(relu(x @ (m*W_v + (1-m)*W_r)))   [attention path is identity:
// softmax rows sum to 1 and the reference einsum contracts the softmax axis]
//   x: [131072, 256] f32,  W: [256, 512] f32,  out: [131072, 512] f32
// Base-sm_103 build (no 'a' features) -> mma.sync bf16, 3-term split.
// CTA = 64 rows x FULL 512 cols so LayerNorm is CTA-local.
// ============================================================================

static constexpr int K_DIM = 256;
static constexpr int N_DIM = 512;
static constexpr int BM    = 64;
static constexpr int KC    = 64;
static constexpr int NCH   = K_DIM / KC;   // 4
static constexpr int M_TOT = 2048 * 64;    // 131072
static constexpr int NT    = 256;          // 8 warps: wm = w>>2 (32 rows), wn = w&3 (128 cols)

// SMEM layout (bytes)
static constexpr int SM_BH = 0;            // B hi: 512 x 128B = 64 KB
static constexpr int SM_BL = 65536;        // B lo: 64 KB
static constexpr int SM_AH = 131072;       // A hi: 64 x 128B = 8 KB
static constexpr int SM_AL = 139264;       // A lo: 8 KB
static constexpr int SM_GB = 147456;       // gamma[512] + beta[512] = 4 KB
static constexpr int SM_PS = 151552;       // psum[256] + psq[256] + stats[128] = 2.5 KB
static constexpr int SMEM_TOTAL = 154624;

// Pre-split combined weights: g_B[split][n][k] bf16, k contiguous
__device__ __align__(16) __nv_bfloat16 g_B[2][N_DIM][K_DIM];

// ---------------------------------------------------------------------------
__device__ __forceinline__ uint32_t smem_u32(const void* p) {
    uint32_t r;
    asm("{ .reg .u64 t; cvta.to.shared.u64 t, %1; cvt.u32.u64 %0, t; }" : "=r"(r) : "l"(p));
    return r;
}
__device__ __forceinline__ uint32_t swz(uint32_t o) { return o ^ ((o >> 3) & 0x70); }

__device__ __forceinline__ void cp16(uint32_t d, const void* s) {
    asm volatile("cp.async.cg.shared.global [%0], [%1], 16;" :: "r"(d), "l"(s));
}
__device__ __forceinline__ void cp_commit() { asm volatile("cp.async.commit_group;"); }
__device__ __forceinline__ void cp_wait0()  { asm volatile("cp.async.wait_group 0;"); }

__device__ __forceinline__ void ldsm4(uint32_t* r, uint32_t a) {
    asm volatile("ldmatrix.sync.aligned.m8n8.x4.shared.b16 {%0,%1,%2,%3}, [%4];"
                 : "=r"(r[0]), "=r"(r[1]), "=r"(r[2]), "=r"(r[3]) : "r"(a));
}
__device__ __forceinline__ void hmma(float* c, const uint32_t* a, const uint32_t* b) {
    asm volatile("mma.sync.aligned.m16n8k16.row.col.f32.bf16.bf16.f32 "
                 "{%0,%1,%2,%3},{%4,%5,%6,%7},{%8,%9},{%0,%1,%2,%3};"
                 : "+f"(c[0]), "+f"(c[1]), "+f"(c[2]), "+f"(c[3])
                 : "r"(a[0]), "r"(a[1]), "r"(a[2]), "r"(a[3]), "r"(b[0]), "r"(b[1]));
}

// ---------------------------------------------------------------------------
// Prep: W_c = m*W_v + (1-m)*W_r, split to bf16 hi/lo, [n][k] images.
// ---------------------------------------------------------------------------
__global__ void prep_kernel(const float* __restrict__ Wv, const float* __restrict__ Wr,
                            const float* __restrict__ mix) {
    int gid = blockIdx.x * blockDim.x + threadIdx.x;
    if (gid >= K_DIM * N_DIM) return;
    int n = gid >> 8;
    int k = gid & 255;
    float m = 1.0f / (1.0f + expf(-mix[0]));
    float w = m * Wv[k * N_DIM + n] + (1.0f - m) * Wr[k * N_DIM + n];
    __nv_bfloat16 hi = __float2bfloat16(w);
    __nv_bfloat16 lo = __float2bfloat16(w - __bfloat162float(hi));
    g_B[0][n][k] = hi;
    g_B[1][n][k] = lo;
}

// ---------------------------------------------------------------------------
// Fused GEMM (3-term bf16 split) + relu + full-width LayerNorm(512)
// ---------------------------------------------------------------------------
__global__ void __launch_bounds__(NT, 1)
gemm_ln_kernel(const float* __restrict__ x, const float* __restrict__ gamma,
               const float* __restrict__ beta, float* __restrict__ out) {
    extern __shared__ char smem[];
    const uint32_t sb = smem_u32(smem);
    const int tid  = threadIdx.x;
    const int warp = tid >> 5;
    const int lane = tid & 31;
    const int wm   = warp >> 2;   // 0..1 -> 32-row half
    const int wn   = warp & 3;    // 0..3 -> 128-col quarter

    const size_t m0 = (size_t)blockIdx.x * BM;

    // gamma/beta into smem
    {
        float* gsh = (float*)(smem + SM_GB);
        for (int i = tid; i < N_DIM; i += NT) {
            gsh[i]         = gamma[i];
            gsh[N_DIM + i] = beta[i];
        }
    }

    // per-thread ldmatrix base offsets (unswizzled)
    const uint32_t arow = (uint32_t)((wm * 32 + (lane & 15)) * 128 + (lane >> 4) * 16);
    const uint32_t brow = (uint32_t)((wn * 128 + ((lane >> 4) & 1) * 8 + (lane & 7)) * 128
                                     + ((lane >> 3) & 1) * 16);

    float acc[2][16][4];
    #pragma unroll
    for (int mt = 0; mt < 2; mt++)
        #pragma unroll
        for (int nt = 0; nt < 16; nt++)
            #pragma unroll
            for (int i = 0; i < 4; i++) acc[mt][nt][i] = 0.0f;

    // prologue: A chunk 0 into regs
    uint4 areg[4];
    #pragma unroll
    for (int i = 0; i < 4; i++) {
        int idx = tid + i * NT;           // 0..1023
        int row = idx >> 4, seg = idx & 15;
        areg[i] = *(const uint4*)(x + (m0 + row) * K_DIM + seg * 4);
    }

    for (int c = 0; c < NCH; c++) {
        // ---- issue B chunk cp.async (8192 x 16B) ----
        #pragma unroll
        for (int i = 0; i < 32; i++) {
            int idx = tid + i * NT;        // 0..8191
            int split = idx >> 12;
            int j = idx & 4095;
            int row = j >> 3, seg = j & 7;
            uint32_t dst = sb + SM_BH + split * 65536 + swz((uint32_t)(row * 128 + seg * 16));
            cp16(dst, &g_B[split][row][c * KC + seg * 8]);
        }
        cp_commit();

        // ---- STS A chunk (split f32 -> bf16 hi/lo, swizzled) ----
        #pragma unroll
        for (int i = 0; i < 4; i++) {
            int idx = tid + i * NT;
            int row = idx >> 4, seg = idx & 15;
            float4 v = *(float4*)&areg[i];
            __nv_bfloat162 h01 = __floats2bfloat162_rn(v.x, v.y);
            __nv_bfloat162 h23 = __floats2bfloat162_rn(v.z, v.w);
            __nv_bfloat162 l01 = __floats2bfloat162_rn(v.x - __bfloat162float(h01.x),
                                                       v.y - __bfloat162float(h01.y));
            __nv_bfloat162 l23 = __floats2bfloat162_rn(v.z - __bfloat162float(h23.x),
                                                       v.w - __bfloat162float(h23.y));
            uint32_t so = swz((uint32_t)(row * 128 + seg * 8));
            *(uint2*)(smem + SM_AH + so) = make_uint2(*(uint32_t*)&h01, *(uint32_t*)&h23);
            *(uint2*)(smem + SM_AL + so) = make_uint2(*(uint32_t*)&l01, *(uint32_t*)&l23);
        }

        // ---- prefetch next A chunk ----
        if (c < NCH - 1) {
            #pragma unroll
            for (int i = 0; i < 4; i++) {
                int idx = tid + i * NT;
                int row = idx >> 4, seg = idx & 15;
                areg[i] = *(const uint4*)(x + (m0 + row) * K_DIM + (c + 1) * KC + seg * 4);
            }
        }

        cp_wait0();
        __syncthreads();

        // ---- MMA: 3 products (Ah*Bh, Al*Bh, Ah*Bl) over 4 k-steps ----
        #pragma unroll
        for (int ks = 0; ks < 4; ks++) {
            uint32_t afh[2][4], afl[2][4];
            #pragma unroll
            for (int mt = 0; mt < 2; mt++)
                ldsm4(afh[mt], sb + SM_AH + swz(arow + mt * 2048 + ks * 32));
            #pragma unroll
            for (int mt = 0; mt < 2; mt++)
                ldsm4(afl[mt], sb + SM_AL + swz(arow + mt * 2048 + ks * 32));
            #pragma unroll
            for (int bt = 0; bt < 8; bt++) {
                uint32_t bh[4], bl[4];
                ldsm4(bh, sb + SM_BH + swz(brow + bt * 2048 + ks * 32));
                #pragma unroll
                for (int mt = 0; mt < 2; mt++) {
                    hmma(acc[mt][2 * bt],     afh[mt], &bh[0]);
                    hmma(acc[mt][2 * bt + 1], afh[mt], &bh[2]);
                }
                #pragma unroll
                for (int mt = 0; mt < 2; mt++) {
                    hmma(acc[mt][2 * bt],     afl[mt], &bh[0]);
                    hmma(acc[mt][2 * bt + 1], afl[mt], &bh[2]);
                }
                ldsm4(bl, sb + SM_BL + swz(brow + bt * 2048 + ks * 32));
                #pragma unroll
                for (int mt = 0; mt < 2; mt++) {
                    hmma(acc[mt][2 * bt],     afh[mt], &bl[0]);
                    hmma(acc[mt][2 * bt + 1], afh[mt], &bl[2]);
                }
            }
        }
        __syncthreads();   // B smem reusable next chunk
    }

    // ------------------- Epilogue: relu + LayerNorm(512) -------------------
    float* psum  = (float*)(smem + SM_PS);   // [64][4]
    float* psq   = psum + 256;               // [64][4]
    float* stats = psum + 512;               // [64][2]

    #pragma unroll
    for (int mt = 0; mt < 2; mt++) {
        #pragma unroll
        for (int half = 0; half < 2; half++) {
            float s = 0.0f, q = 0.0f;
            #pragma unroll
            for (int nt = 0; nt < 16; nt++) {
                float v0 = fmaxf(acc[mt][nt][half * 2 + 0], 0.0f);
                float v1 = fmaxf(acc[mt][nt][half * 2 + 1], 0.0f);
                s += v0 + v1;
                q += v0 * v0 + v1 * v1;
            }
            s += __shfl_xor_sync(0xFFFFFFFFu, s, 1);
            q += __shfl_xor_sync(0xFFFFFFFFu, q, 1);
            s += __shfl_xor_sync(0xFFFFFFFFu, s, 2);
            q += __shfl_xor_sync(0xFFFFFFFFu, q, 2);
            if ((lane & 3) == 0) {
                int r = wm * 32 + mt * 16 + (lane >> 2) + half * 8;
                psum[r * 4 + wn] = s;
                psq[r * 4 + wn]  = q;
            }
        }
    }
    __syncthreads();
    if (tid < BM) {
        float st = psum[tid * 4] + psum[tid * 4 + 1] + psum[tid * 4 + 2] + psum[tid * 4 + 3];
        float qt = psq[tid * 4] + psq[tid * 4 + 1] + psq[tid * 4 + 2] + psq[tid * 4 + 3];
        float mean = st * (1.0f / 512.0f);
        float var  = qt * (1.0f / 512.0f) - mean * mean;
        stats[tid * 2]     = mean;
        stats[tid * 2 + 1] = rsqrtf(var + 1e-5f);
    }
    __syncthreads();

    const float* gsh = (const float*)(smem + SM_GB);
    const float* bsh = gsh + N_DIM;
    #pragma unroll
    for (int mt = 0; mt < 2; mt++) {
        #pragma unroll
        for (int half = 0; half < 2; half++) {
            int r = wm * 32 + mt * 16 + (lane >> 2) + half * 8;
            float mean = stats[r * 2];
            float rstd = stats[r * 2 + 1];
            float* orow = out + (size_t)(m0 + r) * N_DIM;
            #pragma unroll
            for (int nt = 0; nt < 16; nt++) {
                int col = wn * 128 + nt * 8 + (lane & 3) * 2;
                float2 o;
                o.x = (fmaxf(acc[mt][nt][half * 2 + 0], 0.0f) - mean) * rstd * gsh[col]     + bsh[col];
                o.y = (fmaxf(acc[mt][nt][half * 2 + 1], 0.0f) - mean) * rstd * gsh[col + 1] + bsh[col + 1];
                *(float2*)(orow + col) = o;
            }
        }
    }
}

// ---------------------------------------------------------------------------
// Host launcher. Inputs: x, W_q, W_k, W_v, W_r, mix, gamma, beta
// ---------------------------------------------------------------------------
extern "C" void kernel_launch(void* const* d_in, const int* in_sizes, int n_in,
                              void* d_out, int out_size) {
    const float* x     = (const float*)d_in[0];
    const float* Wv    = (const float*)d_in[3];
    const float* Wr    = (const float*)d_in[4];
    const float* mix   = (const float*)d_in[5];
    const float* gamma = (const float*)d_in[6];
    const float* beta  = (const float*)d_in[7];
    float* out = (float*)d_out;

    cudaFuncSetAttribute(gemm_ln_kernel, cudaFuncAttributeMaxDynamicSharedMemorySize, SMEM_TOTAL);

    prep_kernel<<<(K_DIM * N_DIM + 255) / 256, 256>>>(Wv, Wr, mix);
    gemm_ln_kernel<<<M_TOT / BM, NT, SMEM_TOTAL>>>(x, gamma, beta, out);
}

// round 4
// speedup vs baseline: 1.0626x; 1.0626x over previous
#include <cuda_runtime.h>
#include <cuda_bf16.h>
#include <cstdint>

// ============================================================================
// out = LayerNorm(relu(x @ (m*W_v + (1-m)*W_r)))   [attention path is identity:
// softmax rows sum to 1 and the reference einsum contracts the softmax axis]
//   x: [131072, 256] f32,  W: [256, 512] f32,  out: [131072, 512] f32
// mma.sync bf16 3-term split (hi*hi + lo*hi + hi*lo), CTA = 64 rows x 512 cols.
// R4: 16 warps/CTA, KC=32 double-buffered, pre-swizzled packed B images.
// ============================================================================

static constexpr int K_DIM = 256;
static constexpr int N_DIM = 512;
static constexpr int BM    = 64;
static constexpr int KC    = 32;
static constexpr int NCH   = K_DIM / KC;   // 8
static constexpr int M_TOT = 2048 * 64;    // 131072
static constexpr int NT    = 512;          // 16 warps: wm = w>>3 (2 x 32 rows), wn = w&7 (8 x 64 cols)

// SMEM layout (bytes)
// B: packed 2 n-rows per 128B line, 32KB per split per chunk, double buffered
static constexpr int SM_B  = 0;            // buf*65536 + split*32768   -> 128 KB
static constexpr int SM_A  = 131072;       // buf*16384 + split*8192    -> 32 KB (64 rows x 128B, 64B used)
static constexpr int SM_GB = 163840;       // gamma[512] + beta[512] f32 -> 4 KB
static constexpr int SM_PS = 167936;       // psum[64][8] + psq[64][8] + stats[64][2] -> 4.5 KB
static constexpr int SMEM_TOTAL = 172544;

// Pre-swizzled packed B chunk images: exact smem byte layout, linear cp.async
__device__ __align__(16) unsigned char g_Bimg[2][NCH][N_DIM / 2 * 128];  // 2 x 8 x 32KB

// ---------------------------------------------------------------------------
__device__ __forceinline__ uint32_t smem_u32(const void* p) {
    uint32_t r;
    asm("{ .reg .u64 t; cvta.to.shared.u64 t, %1; cvt.u32.u64 %0, t; }" : "=r"(r) : "l"(p));
    return r;
}
__host__ __device__ __forceinline__ uint32_t swz(uint32_t o) { return o ^ ((o >> 3) & 0x70); }

__device__ __forceinline__ void cp16(uint32_t d, const void* s) {
    asm volatile("cp.async.cg.shared.global [%0], [%1], 16;" :: "r"(d), "l"(s));
}
__device__ __forceinline__ void cp_commit() { asm volatile("cp.async.commit_group;"); }
__device__ __forceinline__ void cp_wait0()  { asm volatile("cp.async.wait_group 0;"); }

__device__ __forceinline__ void ldsm4(uint32_t* r, uint32_t a) {
    asm volatile("ldmatrix.sync.aligned.m8n8.x4.shared.b16 {%0,%1,%2,%3}, [%4];"
                 : "=r"(r[0]), "=r"(r[1]), "=r"(r[2]), "=r"(r[3]) : "r"(a));
}
__device__ __forceinline__ void hmma(float* c, const uint32_t* a, const uint32_t* b) {
    asm volatile("mma.sync.aligned.m16n8k16.row.col.f32.bf16.bf16.f32 "
                 "{%0,%1,%2,%3},{%4,%5,%6,%7},{%8,%9},{%0,%1,%2,%3};"
                 : "+f"(c[0]), "+f"(c[1]), "+f"(c[2]), "+f"(c[3])
                 : "r"(a[0]), "r"(a[1]), "r"(a[2]), "r"(a[3]), "r"(b[0]), "r"(b[1]));
}

// ---------------------------------------------------------------------------
// Prep: W_c = m*W_v + (1-m)*W_r, split bf16 hi/lo, write packed pre-swizzled
// chunk images: off(n, kk) = swz( (n>>1)*128 + (n&1)*64 + kk*2 ), kk = k % 32.
// ---------------------------------------------------------------------------
__global__ void prep_kernel(const float* __restrict__ Wv, const float* __restrict__ Wr,
                            const float* __restrict__ mix) {
    int gid = blockIdx.x * blockDim.x + threadIdx.x;
    if (gid >= K_DIM * N_DIM) return;
    int n = gid & 511;
    int k = gid >> 9;
    float m = 1.0f / (1.0f + expf(-mix[0]));
    float w = m * Wv[k * N_DIM + n] + (1.0f - m) * Wr[k * N_DIM + n];
    __nv_bfloat16 hi = __float2bfloat16(w);
    __nv_bfloat16 lo = __float2bfloat16(w - __bfloat162float(hi));
    int c  = k >> 5;
    int kk = k & 31;
    uint32_t off = swz((uint32_t)((n >> 1) * 128 + (n & 1) * 64 + kk * 2));
    *(__nv_bfloat16*)(&g_Bimg[0][c][off]) = hi;
    *(__nv_bfloat16*)(&g_Bimg[1][c][off]) = lo;
}

// ---------------------------------------------------------------------------
// Fused GEMM (3-term bf16 split) + relu + full-width LayerNorm(512)
// ---------------------------------------------------------------------------
__global__ void __launch_bounds__(NT, 1)
gemm_ln_kernel(const float* __restrict__ x, const float* __restrict__ gamma,
               const float* __restrict__ beta, float* __restrict__ out) {
    extern __shared__ char smem[];
    const uint32_t sb = smem_u32(smem);
    const int tid  = threadIdx.x;
    const int warp = tid >> 5;
    const int lane = tid & 31;
    const int wm   = warp >> 3;   // 0..1 -> 32-row half
    const int wn   = warp & 7;    // 0..7 -> 64-col slice

    const size_t m0 = (size_t)blockIdx.x * BM;

    // gamma/beta into smem
    {
        float* gsh = (float*)(smem + SM_GB);
        for (int i = tid; i < N_DIM; i += NT) {
            gsh[i]         = gamma[i];
            gsh[N_DIM + i] = beta[i];
        }
    }

    // per-lane ldmatrix base offsets
    // A (row-major m16k16): row = wm*32 + (lane&15) [+ mt*16], k-16B-half = lane>>4
    const uint32_t arow = (uint32_t)((wm * 32 + (lane & 15)) * 128 + (lane >> 4) * 16);
    // B (col-major n8k16 pairs): n = wn*64 + ((lane>>4)&1)*8 + (lane&7) [+ bt2*16]
    const int nb = wn * 64 + ((lane >> 4) & 1) * 8 + (lane & 7);
    const uint32_t brow = (uint32_t)((nb >> 1) * 128 + (nb & 1) * 64 + ((lane >> 3) & 1) * 16);

    float acc[2][8][4];
    #pragma unroll
    for (int mt = 0; mt < 2; mt++)
        #pragma unroll
        for (int nt = 0; nt < 8; nt++)
            #pragma unroll
            for (int i = 0; i < 4; i++) acc[mt][nt][i] = 0.0f;

    // A STS indices: each thread handles one 4-float segment per chunk
    const int ar  = tid >> 3;        // 0..63  row
    const int as  = tid & 7;         // 0..7   segment (4 floats)
    const uint32_t aso = swz((uint32_t)(ar * 128 + as * 8));

    // ---- prologue ----
    // B chunk 0 cp.async
    #pragma unroll
    for (int i = 0; i < 8; i++) {
        int idx = tid + i * NT;              // 0..4095
        int split = idx >> 11;
        int j = idx & 2047;
        cp16(sb + SM_B + split * 32768 + j * 16, &g_Bimg[split][0][j * 16]);
    }
    cp_commit();
    // A chunk 0: LDG -> split -> STS buf0
    float4 av = *(const float4*)(x + (m0 + ar) * K_DIM + as * 4);
    {
        __nv_bfloat162 h01 = __floats2bfloat162_rn(av.x, av.y);
        __nv_bfloat162 h23 = __floats2bfloat162_rn(av.z, av.w);
        __nv_bfloat162 l01 = __floats2bfloat162_rn(av.x - __bfloat162float(h01.x),
                                                   av.y - __bfloat162float(h01.y));
        __nv_bfloat162 l23 = __floats2bfloat162_rn(av.z - __bfloat162float(h23.x),
                                                   av.w - __bfloat162float(h23.y));
        *(uint2*)(smem + SM_A + aso)        = make_uint2(*(uint32_t*)&h01, *(uint32_t*)&h23);
        *(uint2*)(smem + SM_A + 8192 + aso) = make_uint2(*(uint32_t*)&l01, *(uint32_t*)&l23);
    }
    // prefetch A chunk 1
    av = *(const float4*)(x + (m0 + ar) * K_DIM + KC + as * 4);

    for (int c = 0; c < NCH; c++) {
        const int buf = c & 1;
        cp_wait0();
        __syncthreads();

        if (c < NCH - 1) {
            const int nbuf = buf ^ 1;
            // STS A chunk c+1 (from prefetched regs)
            __nv_bfloat162 h01 = __floats2bfloat162_rn(av.x, av.y);
            __nv_bfloat162 h23 = __floats2bfloat162_rn(av.z, av.w);
            __nv_bfloat162 l01 = __floats2bfloat162_rn(av.x - __bfloat162float(h01.x),
                                                       av.y - __bfloat162float(h01.y));
            __nv_bfloat162 l23 = __floats2bfloat162_rn(av.z - __bfloat162float(h23.x),
                                                       av.w - __bfloat162float(h23.y));
            *(uint2*)(smem + SM_A + nbuf * 16384 + aso)        = make_uint2(*(uint32_t*)&h01, *(uint32_t*)&h23);
            *(uint2*)(smem + SM_A + nbuf * 16384 + 8192 + aso) = make_uint2(*(uint32_t*)&l01, *(uint32_t*)&l23);
            // LDG A chunk c+2
            if (c < NCH - 2)
                av = *(const float4*)(x + (m0 + ar) * K_DIM + (c + 2) * KC + as * 4);
            // cp.async B chunk c+1 (overlaps with MMA below)
            #pragma unroll
            for (int i = 0; i < 8; i++) {
                int idx = tid + i * NT;
                int split = idx >> 11;
                int j = idx & 2047;
                cp16(sb + SM_B + nbuf * 65536 + split * 32768 + j * 16,
                     &g_Bimg[split][c + 1][j * 16]);
            }
            cp_commit();
        }

        // ---- MMA on chunk c: 3 products over 2 k-steps ----
        const uint32_t Ab = sb + SM_A + buf * 16384;
        const uint32_t Bb = sb + SM_B + buf * 65536;
        #pragma unroll
        for (int ks = 0; ks < 2; ks++) {
            uint32_t afh[2][4], afl[2][4];
            #pragma unroll
            for (int mt = 0; mt < 2; mt++)
                ldsm4(afh[mt], Ab + swz(arow + mt * 2048 + ks * 32));
            #pragma unroll
            for (int mt = 0; mt < 2; mt++)
                ldsm4(afl[mt], Ab + 8192 + swz(arow + mt * 2048 + ks * 32));
            #pragma unroll
            for (int bt2 = 0; bt2 < 4; bt2++) {
                uint32_t bh[4], bl[4];
                ldsm4(bh, Bb + swz(brow + bt2 * 1024 + ks * 32));
                #pragma unroll
                for (int mt = 0; mt < 2; mt++) {
                    hmma(acc[mt][2 * bt2],     afh[mt], &bh[0]);
                    hmma(acc[mt][2 * bt2 + 1], afh[mt], &bh[2]);
                    hmma(acc[mt][2 * bt2],     afl[mt], &bh[0]);
                    hmma(acc[mt][2 * bt2 + 1], afl[mt], &bh[2]);
                }
                ldsm4(bl, Bb + 32768 + swz(brow + bt2 * 1024 + ks * 32));
                #pragma unroll
                for (int mt = 0; mt < 2; mt++) {
                    hmma(acc[mt][2 * bt2],     afh[mt], &bl[0]);
                    hmma(acc[mt][2 * bt2 + 1], afh[mt], &bl[2]);
                }
            }
        }
        // no trailing sync: next iteration's cp_wait0 + syncthreads protects buffers
    }

    // ------------------- Epilogue: relu + LayerNorm(512) -------------------
    float* psum  = (float*)(smem + SM_PS);   // [64][8]
    float* psq   = psum + 512;               // [64][8]
    float* stats = psq + 512;                // [64][2]

    #pragma unroll
    for (int mt = 0; mt < 2; mt++) {
        #pragma unroll
        for (int half = 0; half < 2; half++) {
            float s = 0.0f, q = 0.0f;
            #pragma unroll
            for (int nt = 0; nt < 8; nt++) {
                float v0 = fmaxf(acc[mt][nt][half * 2 + 0], 0.0f);
                float v1 = fmaxf(acc[mt][nt][half * 2 + 1], 0.0f);
                s += v0 + v1;
                q += v0 * v0 + v1 * v1;
            }
            s += __shfl_xor_sync(0xFFFFFFFFu, s, 1);
            q += __shfl_xor_sync(0xFFFFFFFFu, q, 1);
            s += __shfl_xor_sync(0xFFFFFFFFu, s, 2);
            q += __shfl_xor_sync(0xFFFFFFFFu, q, 2);
            if ((lane & 3) == 0) {
                int r = wm * 32 + mt * 16 + (lane >> 2) + half * 8;
                psum[r * 8 + wn] = s;
                psq[r * 8 + wn]  = q;
            }
        }
    }
    __syncthreads();
    if (tid < BM) {
        float st = 0.0f, qt = 0.0f;
        #pragma unroll
        for (int i = 0; i < 8; i++) { st += psum[tid * 8 + i]; qt += psq[tid * 8 + i]; }
        float mean = st * (1.0f / 512.0f);
        float var  = qt * (1.0f / 512.0f) - mean * mean;
        stats[tid * 2]     = mean;
        stats[tid * 2 + 1] = rsqrtf(var + 1e-5f);
    }
    __syncthreads();

    const float* gsh = (const float*)(smem + SM_GB);
    const float* bsh = gsh + N_DIM;
    #pragma unroll
    for (int mt = 0; mt < 2; mt++) {
        #pragma unroll
        for (int half = 0; half < 2; half++) {
            int r = wm * 32 + mt * 16 + (lane >> 2) + half * 8;
            float mean = stats[r * 2];
            float rstd = stats[r * 2 + 1];
            float* orow = out + (size_t)(m0 + r) * N_DIM;
            #pragma unroll
            for (int nt = 0; nt < 8; nt++) {
                int col = wn * 64 + nt * 8 + (lane & 3) * 2;
                float2 o;
                o.x = (fmaxf(acc[mt][nt][half * 2 + 0], 0.0f) - mean) * rstd * gsh[col]     + bsh[col];
                o.y = (fmaxf(acc[mt][nt][half * 2 + 1], 0.0f) - mean) * rstd * gsh[col + 1] + bsh[col + 1];
                *(float2*)(orow + col) = o;
            }
        }
    }
}

// ---------------------------------------------------------------------------
// Host launcher. Inputs: x, W_q, W_k, W_v, W_r, mix, gamma, beta
// ---------------------------------------------------------------------------
extern "C" void kernel_launch(void* const* d_in, const int* in_sizes, int n_in,
                              void* d_out, int out_size) {
    const float* x     = (const float*)d_in[0];
    const float* Wv    = (const float*)d_in[3];
    const float* Wr    = (const float*)d_in[4];
    const float* mix   = (const float*)d_in[5];
    const float* gamma = (const float*)d_in[6];
    const float* beta  = (const float*)d_in[7];
    float* out = (float*)d_out;

    cudaFuncSetAttribute(gemm_ln_kernel, cudaFuncAttributeMaxDynamicSharedMemorySize, SMEM_TOTAL);

    prep_kernel<<<(K_DIM * N_DIM + 255) / 256, 256>>>(Wv, Wr, mix);
    gemm_ln_kernel<<<M_TOT / BM, NT, SMEM_TOTAL>>>(x, gamma, beta, out);
}

// round 5
// speedup vs baseline: 1.9860x; 1.8690x over previous
#include <cuda_runtime.h>
#include <cuda_fp16.h>
#include <cstdint>

// ============================================================================
// out = LayerNorm(relu(x @ (m*W_v + (1-m)*W_r)))   [attention path is identity:
// softmax rows sum to 1 and the reference einsum contracts the softmax axis]
//   x: [131072, 256] f32,  W: [256, 512] f32,  out: [131072, 512] f32
// R5: single fp16 mma.sync (11-bit mantissa => ~3e-4 rel err, under 1e-3),
// KC=64 double-buffered, one-ks-ahead register fragment prefetch.
// CTA = 64 rows x 512 cols (LayerNorm CTA-local), 16 warps.
// ============================================================================

static constexpr int K_DIM = 256;
static constexpr int N_DIM = 512;
static constexpr int BM    = 64;
static constexpr int KC    = 64;
static constexpr int NCH   = K_DIM / KC;   // 4
static constexpr int M_TOT = 2048 * 64;    // 131072
static constexpr int NT    = 512;          // 16 warps: wm = w>>3 (2x32 rows), wn = w&7 (8x64 cols)

// SMEM layout (bytes)
static constexpr int SM_B  = 0;            // 2 bufs x (512 n-rows x 128B) = 128 KB
static constexpr int SM_A  = 131072;       // 2 bufs x (64 rows x 128B)    = 16 KB
static constexpr int SM_GB = 147456;       // gamma[512]+beta[512] f32     = 4 KB
static constexpr int SM_PS = 151552;       // psum[64][8]+psq[64][8]+stats = 4.5 KB
static constexpr int SMEM_TOTAL = 156160;

// Pre-swizzled fp16 B chunk images: exact smem byte layout, linear cp.async.
// off(n, kk) = swz(n*128 + kk*2), kk = k % 64, chunk = k / 64.
__device__ __align__(16) unsigned char g_Bimg[NCH][N_DIM * 128];

// ---------------------------------------------------------------------------
__device__ __forceinline__ uint32_t smem_u32(const void* p) {
    uint32_t r;
    asm("{ .reg .u64 t; cvta.to.shared.u64 t, %1; cvt.u32.u64 %0, t; }" : "=r"(r) : "l"(p));
    return r;
}
__host__ __device__ __forceinline__ uint32_t swz(uint32_t o) { return o ^ ((o >> 3) & 0x70); }

__device__ __forceinline__ void cp16(uint32_t d, const void* s) {
    asm volatile("cp.async.cg.shared.global [%0], [%1], 16;" :: "r"(d), "l"(s));
}
__device__ __forceinline__ void cp_commit() { asm volatile("cp.async.commit_group;"); }
__device__ __forceinline__ void cp_wait0()  { asm volatile("cp.async.wait_group 0;"); }

__device__ __forceinline__ void ldsm4(uint32_t* r, uint32_t a) {
    asm volatile("ldmatrix.sync.aligned.m8n8.x4.shared.b16 {%0,%1,%2,%3}, [%4];"
                 : "=r"(r[0]), "=r"(r[1]), "=r"(r[2]), "=r"(r[3]) : "r"(a));
}
__device__ __forceinline__ void hmma(float* c, const uint32_t* a, const uint32_t* b) {
    asm volatile("mma.sync.aligned.m16n8k16.row.col.f32.f16.f16.f32 "
                 "{%0,%1,%2,%3},{%4,%5,%6,%7},{%8,%9},{%0,%1,%2,%3};"
                 : "+f"(c[0]), "+f"(c[1]), "+f"(c[2]), "+f"(c[3])
                 : "r"(a[0]), "r"(a[1]), "r"(a[2]), "r"(a[3]), "r"(b[0]), "r"(b[1]));
}

// ---------------------------------------------------------------------------
// Prep: W_c = m*W_v + (1-m)*W_r -> fp16, pre-swizzled chunk images.
// ---------------------------------------------------------------------------
__global__ void prep_kernel(const float* __restrict__ Wv, const float* __restrict__ Wr,
                            const float* __restrict__ mix) {
    int gid = blockIdx.x * blockDim.x + threadIdx.x;
    if (gid >= K_DIM * N_DIM) return;
    int n = gid & 511;
    int k = gid >> 9;
    float m = 1.0f / (1.0f + expf(-mix[0]));
    float w = m * Wv[k * N_DIM + n] + (1.0f - m) * Wr[k * N_DIM + n];
    int c  = k >> 6;
    int kk = k & 63;
    uint32_t off = swz((uint32_t)(n * 128 + kk * 2));
    *(__half*)(&g_Bimg[c][off]) = __float2half(w);
}

// ---------------------------------------------------------------------------
// Fused GEMM (fp16 mma.sync) + relu + full-width LayerNorm(512)
// ---------------------------------------------------------------------------
__global__ void __launch_bounds__(NT, 1)
gemm_ln_kernel(const float* __restrict__ x, const float* __restrict__ gamma,
               const float* __restrict__ beta, float* __restrict__ out) {
    extern __shared__ char smem[];
    const uint32_t sb = smem_u32(smem);
    const int tid  = threadIdx.x;
    const int warp = tid >> 5;
    const int lane = tid & 31;
    const int wm   = warp >> 3;   // 0..1 -> 32-row half
    const int wn   = warp & 7;    // 0..7 -> 64-col slice

    const size_t m0 = (size_t)blockIdx.x * BM;

    // gamma/beta into smem
    {
        float* gsh = (float*)(smem + SM_GB);
        for (int i = tid; i < N_DIM; i += NT) {
            gsh[i]         = gamma[i];
            gsh[N_DIM + i] = beta[i];
        }
    }

    // per-lane ldmatrix base offsets (verified pattern from R3/R4)
    const uint32_t arow = (uint32_t)((wm * 32 + (lane & 15)) * 128 + (lane >> 4) * 16);
    const uint32_t brow = (uint32_t)((wn * 64 + ((lane >> 4) & 1) * 8 + (lane & 7)) * 128
                                     + ((lane >> 3) & 1) * 16);

    float acc[2][8][4];
    #pragma unroll
    for (int mt = 0; mt < 2; mt++)
        #pragma unroll
        for (int nt = 0; nt < 8; nt++)
            #pragma unroll
            for (int i = 0; i < 4; i++) acc[mt][nt][i] = 0.0f;

    // A load/STS indexing: 1024 float4 per chunk, 2 per thread
    const int ar0 = tid >> 3;              // via idx = tid + i*NT: rows 0..63
    const int as0 = tid & 7;               // seg pattern below

    // ---- prologue: B chunk0 cp.async, A chunk0 LDG->STS, A chunk1 LDG ----
    #pragma unroll
    for (int i = 0; i < 8; i++) {
        int j = tid + i * NT;              // 0..4095
        cp16(sb + SM_B + j * 16, &g_Bimg[0][j * 16]);
    }
    cp_commit();

    float4 av[2];
    #pragma unroll
    for (int i = 0; i < 2; i++) {
        int idx = tid + i * NT;
        int row = idx >> 4, seg = idx & 15;
        av[i] = *(const float4*)(x + (m0 + row) * K_DIM + seg * 4);
    }
    #pragma unroll
    for (int i = 0; i < 2; i++) {
        int idx = tid + i * NT;
        int row = idx >> 4, seg = idx & 15;
        __half2 h01 = __floats2half2_rn(av[i].x, av[i].y);
        __half2 h23 = __floats2half2_rn(av[i].z, av[i].w);
        *(uint2*)(smem + SM_A + swz((uint32_t)(row * 128 + seg * 8))) =
            make_uint2(*(uint32_t*)&h01, *(uint32_t*)&h23);
    }
    #pragma unroll
    for (int i = 0; i < 2; i++) {
        int idx = tid + i * NT;
        int row = idx >> 4, seg = idx & 15;
        av[i] = *(const float4*)(x + (m0 + row) * K_DIM + KC + seg * 4);
    }

    for (int c = 0; c < NCH; c++) {
        const int buf = c & 1;
        cp_wait0();
        __syncthreads();

        if (c < NCH - 1) {
            const int nbuf = buf ^ 1;
            // STS A chunk c+1 from prefetched regs
            #pragma unroll
            for (int i = 0; i < 2; i++) {
                int idx = tid + i * NT;
                int row = idx >> 4, seg = idx & 15;
                __half2 h01 = __floats2half2_rn(av[i].x, av[i].y);
                __half2 h23 = __floats2half2_rn(av[i].z, av[i].w);
                *(uint2*)(smem + SM_A + nbuf * 8192 + swz((uint32_t)(row * 128 + seg * 8))) =
                    make_uint2(*(uint32_t*)&h01, *(uint32_t*)&h23);
            }
            // LDG A chunk c+2
            if (c < NCH - 2) {
                #pragma unroll
                for (int i = 0; i < 2; i++) {
                    int idx = tid + i * NT;
                    int row = idx >> 4, seg = idx & 15;
                    av[i] = *(const float4*)(x + (m0 + row) * K_DIM + (c + 2) * KC + seg * 4);
                }
            }
            // B chunk c+1 cp.async (overlaps with MMA below)
            #pragma unroll
            for (int i = 0; i < 8; i++) {
                int j = tid + i * NT;
                cp16(sb + SM_B + nbuf * 65536 + j * 16, &g_Bimg[c + 1][j * 16]);
            }
            cp_commit();
        }

        // ---- MMA chunk c: 4 k-steps, one-ks-ahead fragment prefetch ----
        const uint32_t Ab = sb + SM_A + buf * 8192;
        const uint32_t Bb = sb + SM_B + buf * 65536;
        uint32_t af[2][2][4], bf[2][4][4];
        #pragma unroll
        for (int mt = 0; mt < 2; mt++)
            ldsm4(af[0][mt], Ab + swz(arow + mt * 2048));
        #pragma unroll
        for (int bt = 0; bt < 4; bt++)
            ldsm4(bf[0][bt], Bb + swz(brow + bt * 2048));
        #pragma unroll
        for (int ks = 0; ks < 4; ks++) {
            const int cur = ks & 1, nxt = cur ^ 1;
            if (ks < 3) {
                #pragma unroll
                for (int mt = 0; mt < 2; mt++)
                    ldsm4(af[nxt][mt], Ab + swz(arow + mt * 2048 + (ks + 1) * 32));
                #pragma unroll
                for (int bt = 0; bt < 4; bt++)
                    ldsm4(bf[nxt][bt], Bb + swz(brow + bt * 2048 + (ks + 1) * 32));
            }
            #pragma unroll
            for (int bt = 0; bt < 4; bt++)
                #pragma unroll
                for (int mt = 0; mt < 2; mt++) {
                    hmma(acc[mt][2 * bt],     af[cur][mt], &bf[cur][bt][0]);
                    hmma(acc[mt][2 * bt + 1], af[cur][mt], &bf[cur][bt][2]);
                }
        }
        // next iteration's cp_wait0 + __syncthreads protects buffer reuse
    }

    // ------------------- Epilogue: relu + LayerNorm(512) -------------------
    float* psum  = (float*)(smem + SM_PS);   // [64][8]
    float* psq   = psum + 512;               // [64][8]
    float* stats = psq + 512;                // [64][2]

    #pragma unroll
    for (int mt = 0; mt < 2; mt++) {
        #pragma unroll
        for (int half = 0; half < 2; half++) {
            float s = 0.0f, q = 0.0f;
            #pragma unroll
            for (int nt = 0; nt < 8; nt++) {
                float v0 = fmaxf(acc[mt][nt][half * 2 + 0], 0.0f);
                float v1 = fmaxf(acc[mt][nt][half * 2 + 1], 0.0f);
                s += v0 + v1;
                q += v0 * v0 + v1 * v1;
            }
            s += __shfl_xor_sync(0xFFFFFFFFu, s, 1);
            q += __shfl_xor_sync(0xFFFFFFFFu, q, 1);
            s += __shfl_xor_sync(0xFFFFFFFFu, s, 2);
            q += __shfl_xor_sync(0xFFFFFFFFu, q, 2);
            if ((lane & 3) == 0) {
                int r = wm * 32 + mt * 16 + (lane >> 2) + half * 8;
                psum[r * 8 + wn] = s;
                psq[r * 8 + wn]  = q;
            }
        }
    }
    __syncthreads();
    if (tid < BM) {
        float st = 0.0f, qt = 0.0f;
        #pragma unroll
        for (int i = 0; i < 8; i++) { st += psum[tid * 8 + i]; qt += psq[tid * 8 + i]; }
        float mean = st * (1.0f / 512.0f);
        float var  = qt * (1.0f / 512.0f) - mean * mean;
        stats[tid * 2]     = mean;
        stats[tid * 2 + 1] = rsqrtf(var + 1e-5f);
    }
    __syncthreads();

    const float* gsh = (const float*)(smem + SM_GB);
    const float* bsh = gsh + N_DIM;
    #pragma unroll
    for (int mt = 0; mt < 2; mt++) {
        #pragma unroll
        for (int half = 0; half < 2; half++) {
            int r = wm * 32 + mt * 16 + (lane >> 2) + half * 8;
            float mean = stats[r * 2];
            float rstd = stats[r * 2 + 1];
            float* orow = out + (size_t)(m0 + r) * N_DIM;
            #pragma unroll
            for (int nt = 0; nt < 8; nt++) {
                int col = wn * 64 + nt * 8 + (lane & 3) * 2;
                float2 o;
                o.x = (fmaxf(acc[mt][nt][half * 2 + 0], 0.0f) - mean) * rstd * gsh[col]     + bsh[col];
                o.y = (fmaxf(acc[mt][nt][half * 2 + 1], 0.0f) - mean) * rstd * gsh[col + 1] + bsh[col + 1];
                *(float2*)(orow + col) = o;
            }
        }
    }
}

// ---------------------------------------------------------------------------
// Host launcher. Inputs: x, W_q, W_k, W_v, W_r, mix, gamma, beta
// ---------------------------------------------------------------------------
extern "C" void kernel_launch(void* const* d_in, const int* in_sizes, int n_in,
                              void* d_out, int out_size) {
    const float* x     = (const float*)d_in[0];
    const float* Wv    = (const float*)d_in[3];
    const float* Wr    = (const float*)d_in[4];
    const float* mix   = (const float*)d_in[5];
    const float* gamma = (const float*)d_in[6];
    const float* beta  = (const float*)d_in[7];
    float* out = (float*)d_out;

    cudaFuncSetAttribute(gemm_ln_kernel, cudaFuncAttributeMaxDynamicSharedMemorySize, SMEM_TOTAL);

    prep_kernel<<<(K_DIM * N_DIM + 255) / 256, 256>>>(Wv, Wr, mix);
    gemm_ln_kernel<<<M_TOT / BM, NT, SMEM_TOTAL>>>(x, gamma, beta, out);
}